// round 10
// baseline (speedup 1.0000x reference)
#include <cuda_runtime.h>
#include <cuda_bf16.h>
#include <math.h>
#include <stdint.h>

#define NB 4
#define SQ 2048
#define HD 512
#define BSH (NB * SQ * HD)
#define KSCALE 0.044194173824159216f
#define TB 8192             // one tile: 128 rows * 64 bytes (swizzled)
#define STG3 (4 * TB)       // 4 tiles per stage = 32KB
#define SMEM_BYTES (3 * STG3)   // 98304

typedef __nv_bfloat16 bf16;
struct __align__(8) bf4 { __nv_bfloat162 a, b; };

// ---- scratch ----
__device__ float g_sf[2][BSH];
__device__ bf16  g_sh[2][BSH], g_sl[2][BSH];
__device__ bf16  g_xh[BSH], g_xl[BSH];
__device__ bf16  g_kh[BSH], g_kl[BSH];
__device__ bf16  g_kth[BSH], g_ktl[BSH];
__device__ bf16  g_vth[BSH], g_vtl[BSH];
__device__ bf16  g_ath[BSH], g_atl[BSH];
__device__ bf16  g_wh[4 * HD * HD], g_wl[4 * HD * HD];
__device__ float g_tmpf[BSH];
__device__ float g_scores[(size_t)NB * SQ * SQ];
__device__ bf16  g_ph[(size_t)NB * SQ * SQ], g_pl[(size_t)NB * SQ * SQ];
__device__ int   g_converged, g_iters, g_sel;
__device__ float g_sumd, g_sumn;

// ---- helpers ----
__device__ __forceinline__ uint32_t smem_u32(const void* p) {
    uint32_t a;
    asm("{ .reg .u64 t; cvta.to.shared.u64 t, %1; cvt.u32.u64 %0, t; }" : "=r"(a) : "l"(p));
    return a;
}
__device__ __forceinline__ void ldsm4(uint32_t* r, uint32_t addr) {
    asm volatile("ldmatrix.sync.aligned.m8n8.x4.shared.b16 {%0,%1,%2,%3}, [%4];"
                 : "=r"(r[0]), "=r"(r[1]), "=r"(r[2]), "=r"(r[3]) : "r"(addr));
}
__device__ __forceinline__ void mma16816(float* d, const uint32_t* a, const uint32_t* b) {
    asm volatile(
        "mma.sync.aligned.m16n8k16.row.col.f32.bf16.bf16.f32 "
        "{%0,%1,%2,%3}, {%4,%5,%6,%7}, {%8,%9}, {%0,%1,%2,%3};"
        : "+f"(d[0]), "+f"(d[1]), "+f"(d[2]), "+f"(d[3])
        : "r"(a[0]), "r"(a[1]), "r"(a[2]), "r"(a[3]), "r"(b[0]), "r"(b[1]));
}
__device__ __forceinline__ void cpa16(uint32_t s, const void* g) {
    asm volatile("cp.async.cg.shared.global [%0], [%1], 16;" :: "r"(s), "l"(g));
}
__device__ __forceinline__ void split2(float v, bf16& h, bf16& l) {
    h = __float2bfloat16(v);
    l = __float2bfloat16(v - __bfloat162float(h));
}
// swizzled smem offset for (row, 16B-segment)
__device__ __forceinline__ uint32_t swz(int row, int seg) {
    return (uint32_t)(row * 64 + ((seg ^ ((row >> 1) & 3)) << 4));
}

// ---- control ----
__global__ void k_init() {
    g_converged = 0; g_iters = 0; g_sel = 0; g_sumd = 0.0f; g_sumn = 0.0f;
}
__global__ void k_finalize() {
    if (g_converged) return;
    float delta = sqrtf(g_sumd) / (sqrtf(g_sumn) + 1e-8f);
    g_iters += 1;
    if (delta < 1e-4f) g_converged = 1;
    g_sel ^= 1;
    g_sumd = 0.0f; g_sumn = 0.0f;
}
__global__ void k_tail(float* out, int extra) {
    if (extra >= 1) out[BSH] = (float)g_iters;
    if (extra >= 2) out[BSH + 1] = g_converged ? 1.0f : 0.0f;
}

// ---- fused fp32 -> (hi,lo) bf16 for x + 4 weights ----
__global__ void k_cvt_all(const float* __restrict__ x,
                          const float* __restrict__ Wq, const float* __restrict__ Wk,
                          const float* __restrict__ Wv, const float* __restrict__ Wo) {
    const int nwb = (HD * HD) / 1024;
    int b = blockIdx.x;
    const float* src;
    bf16 *h, *l;
    int base;
    if (b < BSH / 1024) {
        src = x; h = g_xh; l = g_xl; base = b * 1024;
    } else {
        int wb = b - BSH / 1024;
        int wi = wb / nwb;
        base = (wb - wi * nwb) * 1024;
        src = (wi == 0) ? Wq : (wi == 1) ? Wk : (wi == 2) ? Wv : Wo;
        h = g_wh + wi * HD * HD; l = g_wl + wi * HD * HD;
    }
    int i = base + threadIdx.x * 4;
    float4 v = *(const float4*)(src + i);
    bf4 hv, lv;
    split2(v.x, hv.a.x, lv.a.x);
    split2(v.y, hv.a.y, lv.a.y);
    split2(v.z, hv.b.x, lv.b.x);
    split2(v.w, hv.b.y, lv.b.y);
    *(bf4*)(h + i) = hv;
    *(bf4*)(l + i) = lv;
}

// ---- transpose-convert fp32 [B,S,H] -> bf16 hi/lo [B,H,S] ----
__global__ void k_tcvt(const float* __restrict__ src, bf16* __restrict__ th,
                       bf16* __restrict__ tl) {
    __shared__ float t[32][33];
    const int z = blockIdx.z;
    const float* s = src + (size_t)z * SQ * HD;
    const int h0 = blockIdx.x * 32, s0 = blockIdx.y * 32;
    const int tx = threadIdx.x, ty = threadIdx.y;
    for (int r = ty; r < 32; r += 8) t[r][tx] = s[(size_t)(s0 + r) * HD + h0 + tx];
    __syncthreads();
    for (int r = ty; r < 32; r += 8) {
        float v = t[tx][r];
        size_t o = (size_t)z * HD * SQ + (size_t)(h0 + r) * SQ + s0 + tx;
        bf16 hh, ll;
        split2(v, hh, ll);
        th[o] = hh;
        tl[o] = ll;
    }
}

// ---- register softmax: row of 2048, 256 threads ----
__global__ void __launch_bounds__(256)
k_softmax(int guard) {
    if (guard && g_converged) return;
    const size_t base = (size_t)blockIdx.x * SQ;
    const float4* r4 = (const float4*)(g_scores + base);
    const int tid = threadIdx.x, lane = tid & 31, w = tid >> 5;
    __shared__ float wr[16];

    float4 a = r4[tid], b = r4[tid + 256];
    float m = fmaxf(fmaxf(fmaxf(a.x, a.y), fmaxf(a.z, a.w)),
                    fmaxf(fmaxf(b.x, b.y), fmaxf(b.z, b.w)));
#pragma unroll
    for (int o = 16; o; o >>= 1) m = fmaxf(m, __shfl_xor_sync(0xffffffffu, m, o));
    if (lane == 0) wr[w] = m;
    __syncthreads();
    float mm = wr[0];
#pragma unroll
    for (int i = 1; i < 8; i++) mm = fmaxf(mm, wr[i]);

    float e[8];
    e[0] = __expf(a.x - mm); e[1] = __expf(a.y - mm);
    e[2] = __expf(a.z - mm); e[3] = __expf(a.w - mm);
    e[4] = __expf(b.x - mm); e[5] = __expf(b.y - mm);
    e[6] = __expf(b.z - mm); e[7] = __expf(b.w - mm);
    float s = e[0] + e[1] + e[2] + e[3] + e[4] + e[5] + e[6] + e[7];
#pragma unroll
    for (int o = 16; o; o >>= 1) s += __shfl_xor_sync(0xffffffffu, s, o);
    if (lane == 0) wr[8 + w] = s;
    __syncthreads();
    float tot = 0.0f;
#pragma unroll
    for (int i = 0; i < 8; i++) tot += wr[8 + i];
    const float inv = 1.0f / tot;

    bf4* ph4 = (bf4*)(g_ph + base);
    bf4* pl4 = (bf4*)(g_pl + base);
#pragma unroll
    for (int g = 0; g < 2; g++) {
        bf4 hv, lv;
        split2(e[g * 4 + 0] * inv, hv.a.x, lv.a.x);
        split2(e[g * 4 + 1] * inv, hv.a.y, lv.a.y);
        split2(e[g * 4 + 2] * inv, hv.b.x, lv.b.x);
        split2(e[g * 4 + 3] * inv, hv.b.y, lv.b.y);
        ph4[tid + g * 256] = hv;
        pl4[tid + g * 256] = lv;
    }
}

// ---- cp.async one 128x32 bf16 tile into swizzled smem (64B rows) ----
__device__ __forceinline__ void cpa_tile(uint32_t sdst, const bf16* __restrict__ src,
                                         size_t row0, int k0, int ld, int tid) {
#pragma unroll
    for (int r = 0; r < 2; r++) {
        int seg = tid + r * 256;
        int row = seg >> 2, sc = seg & 3;
        cpa16(sdst + swz(row, sc),
              src + (row0 + row) * (size_t)ld + k0 + sc * 8);
    }
}

// ---- split-bf16 HMMA GEMM: C[128,128] = A[128,K] @ B[128,K]^T ----
// 3-stage cp.async pipeline, one __syncthreads per K-chunk (wait BEFORE barrier)
__global__ void __launch_bounds__(256, 2)
k_gemm(const bf16* __restrict__ Ah_, const bf16* __restrict__ Al_,
       const bf16* __restrict__ Bh_, const bf16* __restrict__ Bl_,
       float* Cf, bf16* Ch, bf16* Cl,
       const float* __restrict__ bias, float scale, int Ktot, int ldc,
       size_t aB, size_t bB, size_t cB, int am, int cm, int guard) {
    if (guard && g_converged) return;
    extern __shared__ char smem[];
    const uint32_t sb = smem_u32(smem);
    const int tid = threadIdx.x, lane = tid & 31, w = tid >> 5;
    const int warp_m = (w >> 1) * 32, warp_n = (w & 1) * 64;

    const int z = blockIdx.z;
    const bf16 *Ah = Ah_, *Al = Al_;
    if (am) { int s = g_sel; Ah = g_sh[s]; Al = g_sl[s]; }
    Ah += (size_t)z * aB; Al += (size_t)z * aB;
    const bf16* Bh = Bh_ + (size_t)z * bB;
    const bf16* Bl = Bl_ + (size_t)z * bB;
    const float* Cold = nullptr;
    if (cm) {
        int s = g_sel ^ 1;
        Cf = g_sf[s]; Ch = g_sh[s]; Cl = g_sl[s];
        Cold = g_sf[s ^ 1] + (size_t)z * cB;
    }
    if (Cf) Cf += (size_t)z * cB;
    if (Ch) { Ch += (size_t)z * cB; Cl += (size_t)z * cB; }

    const size_t row0 = (size_t)blockIdx.y * 128;
    const size_t nrow0 = (size_t)blockIdx.x * 128;
    const int n0 = blockIdx.x * 128;

    // swizzled ldmatrix base offsets (k16 step applied as XOR 32)
    uint32_t offA[2], offB[4];
#pragma unroll
    for (int mt = 0; mt < 2; mt++) {
        int row = warp_m + mt * 16 + (lane & 7) + 8 * ((lane >> 3) & 1);
        offA[mt] = swz(row, (lane >> 4) & 1);
    }
#pragma unroll
    for (int p = 0; p < 4; p++) {
        int row = warp_n + p * 16 + (lane & 7) + 8 * (lane >> 4);
        offB[p] = swz(row, (lane >> 3) & 1);
    }

    float acc[2][8][4];
#pragma unroll
    for (int mt = 0; mt < 2; mt++)
#pragma unroll
        for (int nt = 0; nt < 8; nt++)
#pragma unroll
            for (int i = 0; i < 4; i++) acc[mt][nt][i] = 0.0f;

    const int nch = Ktot >> 5;
    // prologue: chunks 0,1 into stages 0,1
    cpa_tile(sb,          Ah, row0,  0, Ktot, tid);
    cpa_tile(sb + TB,     Al, row0,  0, Ktot, tid);
    cpa_tile(sb + 2 * TB, Bh, nrow0, 0, Ktot, tid);
    cpa_tile(sb + 3 * TB, Bl, nrow0, 0, Ktot, tid);
    asm volatile("cp.async.commit_group;");
    {
        uint32_t s1 = sb + STG3;
        cpa_tile(s1,          Ah, row0,  32, Ktot, tid);
        cpa_tile(s1 + TB,     Al, row0,  32, Ktot, tid);
        cpa_tile(s1 + 2 * TB, Bh, nrow0, 32, Ktot, tid);
        cpa_tile(s1 + 3 * TB, Bl, nrow0, 32, Ktot, tid);
        asm volatile("cp.async.commit_group;");
    }

    int cur = 0, nxt2 = 2;       // stage of chunk c, stage for chunk c+2
    for (int c = 0; c < nch; c++) {
        // my chunk-c copies done (outstanding: c, c+1) ...
        if (c + 1 < nch) { asm volatile("cp.async.wait_group 1;"); }
        else             { asm volatile("cp.async.wait_group 0;"); }
        // ... then publish to all threads; also proves all warps finished chunk c-1
        __syncthreads();
        // safe now to overwrite stage nxt2 (last read at chunk c-1)
        if (c + 2 < nch) {
            uint32_t s2 = sb + nxt2 * STG3;
            int k0 = (c + 2) << 5;
            cpa_tile(s2,          Ah, row0,  k0, Ktot, tid);
            cpa_tile(s2 + TB,     Al, row0,  k0, Ktot, tid);
            cpa_tile(s2 + 2 * TB, Bh, nrow0, k0, Ktot, tid);
            cpa_tile(s2 + 3 * TB, Bl, nrow0, k0, Ktot, tid);
            asm volatile("cp.async.commit_group;");
        }

        const uint32_t ss = sb + cur * STG3;
#pragma unroll
        for (int k16 = 0; k16 < 2; k16++) {
            const uint32_t kof = k16 * 32;   // XOR into swizzled addr
            uint32_t ah0[4], al0[4], ah1[4], al1[4];
            ldsm4(ah0, ss + (offA[0] ^ kof));
            ldsm4(al0, ss + TB + (offA[0] ^ kof));
            ldsm4(ah1, ss + (offA[1] ^ kof));
            ldsm4(al1, ss + TB + (offA[1] ^ kof));
#pragma unroll
            for (int p = 0; p < 4; p++) {
                uint32_t bh[4], bl[4];
                ldsm4(bh, ss + 2 * TB + (offB[p] ^ kof));
                ldsm4(bl, ss + 3 * TB + (offB[p] ^ kof));
#pragma unroll
                for (int sub = 0; sub < 2; sub++) {
                    const uint32_t* pbh = &bh[sub * 2];
                    const uint32_t* pbl = &bl[sub * 2];
                    int nt = p * 2 + sub;
                    mma16816(acc[0][nt], ah0, pbh);
                    mma16816(acc[0][nt], ah0, pbl);
                    mma16816(acc[0][nt], al0, pbh);
                    mma16816(acc[1][nt], ah1, pbh);
                    mma16816(acc[1][nt], ah1, pbl);
                    mma16816(acc[1][nt], al1, pbh);
                }
            }
        }
        cur = (cur == 2) ? 0 : cur + 1;
        nxt2 = (nxt2 == 2) ? 0 : nxt2 + 1;
    }
    __syncthreads();   // protect smem (rbuf) reuse below vs last compute

    // epilogue (+ fused Frobenius-delta partials when writing state)
    float sd = 0.0f, sn = 0.0f;
    const int cr = lane >> 2, cc = (lane & 3) * 2;
#pragma unroll
    for (int mt = 0; mt < 2; mt++) {
#pragma unroll
        for (int nt = 0; nt < 8; nt++) {
#pragma unroll
            for (int half = 0; half < 2; half++) {
                int row = warp_m + mt * 16 + cr + half * 8;
                int col = warp_n + nt * 8 + cc;
                float vx = acc[mt][nt][half * 2 + 0] * scale;
                float vy = acc[mt][nt][half * 2 + 1] * scale;
                int gc = n0 + col;
                if (bias) { vx += __ldg(bias + gc); vy += __ldg(bias + gc + 1); }
                size_t ci = (row0 + row) * (size_t)ldc + gc;
                if (Cf) { float2 o; o.x = vx; o.y = vy; *(float2*)(Cf + ci) = o; }
                if (Cold) {
                    float2 ov = *(const float2*)(Cold + ci);
                    float dx = vx - ov.x, dy = vy - ov.y;
                    sd += dx * dx + dy * dy;
                    sn += ov.x * ov.x + ov.y * ov.y;
                }
                if (Ch) {
                    __nv_bfloat162 hv, lv;
                    split2(vx, hv.x, lv.x);
                    split2(vy, hv.y, lv.y);
                    *(__nv_bfloat162*)(Ch + ci) = hv;
                    *(__nv_bfloat162*)(Cl + ci) = lv;
                }
            }
        }
    }
    if (Cold) {
#pragma unroll
        for (int o = 16; o; o >>= 1) {
            sd += __shfl_xor_sync(0xffffffffu, sd, o);
            sn += __shfl_xor_sync(0xffffffffu, sn, o);
        }
        float* rbuf = (float*)smem;
        if (lane == 0) { rbuf[w] = sd; rbuf[8 + w] = sn; }
        __syncthreads();
        if (tid == 0) {
            float t1 = 0.0f, t2 = 0.0f;
#pragma unroll
            for (int i = 0; i < 8; i++) { t1 += rbuf[i]; t2 += rbuf[8 + i]; }
            atomicAdd(&g_sumd, t1);
            atomicAdd(&g_sumn, t2);
        }
    }
}

// ---- launch ----
extern "C" void kernel_launch(void* const* d_in, const int* in_sizes, int n_in,
                              void* d_out, int out_size) {
    const float* x  = (const float*)d_in[0];
    const float* Wq = (const float*)d_in[1];
    const float* bq = (const float*)d_in[2];
    const float* Wk = (const float*)d_in[3];
    const float* bk = (const float*)d_in[4];
    const float* Wv = (const float*)d_in[5];
    const float* bv = (const float*)d_in[6];
    const float* Wo = (const float*)d_in[7];
    const float* bo = (const float*)d_in[8];
    float* out = (float*)d_out;

    void* pv;
    cudaGetSymbolAddress(&pv, g_xh);   bf16* xh = (bf16*)pv;
    cudaGetSymbolAddress(&pv, g_xl);   bf16* xl = (bf16*)pv;
    cudaGetSymbolAddress(&pv, g_kh);   bf16* kh = (bf16*)pv;
    cudaGetSymbolAddress(&pv, g_kl);   bf16* kl = (bf16*)pv;
    cudaGetSymbolAddress(&pv, g_kth);  bf16* kth = (bf16*)pv;
    cudaGetSymbolAddress(&pv, g_ktl);  bf16* ktl = (bf16*)pv;
    cudaGetSymbolAddress(&pv, g_vth);  bf16* vth = (bf16*)pv;
    cudaGetSymbolAddress(&pv, g_vtl);  bf16* vtl = (bf16*)pv;
    cudaGetSymbolAddress(&pv, g_ath);  bf16* ath = (bf16*)pv;
    cudaGetSymbolAddress(&pv, g_atl);  bf16* atl = (bf16*)pv;
    cudaGetSymbolAddress(&pv, g_wh);   bf16* wh = (bf16*)pv;
    cudaGetSymbolAddress(&pv, g_wl);   bf16* wl = (bf16*)pv;
    cudaGetSymbolAddress(&pv, g_tmpf); float* tmpf = (float*)pv;
    cudaGetSymbolAddress(&pv, g_scores); float* sc = (float*)pv;
    cudaGetSymbolAddress(&pv, g_ph);   bf16* ph = (bf16*)pv;
    cudaGetSymbolAddress(&pv, g_pl);   bf16* pl = (bf16*)pv;
    cudaGetSymbolAddress(&pv, g_sf);   float* sf0 = (float*)pv;
    cudaGetSymbolAddress(&pv, g_sh);   bf16* sh0 = (bf16*)pv;
    cudaGetSymbolAddress(&pv, g_sl);   bf16* sl0 = (bf16*)pv;

    cudaFuncSetAttribute(k_gemm, cudaFuncAttributeMaxDynamicSharedMemorySize, SMEM_BYTES);

    const int nw = HD * HD;
    const dim3 gP(4, 64, 1);
    const dim3 gS(16, 16, 4);
    const dim3 gV(4, 16, 4);
    const dim3 gT(16, 64, 4);
    const dim3 bT(32, 8);
    const size_t aS = (size_t)SQ * HD, cS = (size_t)SQ * SQ;

    k_init<<<1, 1>>>();
    k_cvt_all<<<BSH / 1024 + 4 * (nw / 1024), 256>>>(x, Wq, Wk, Wv, Wo);

    // q -> state slot 0 (fp32 + hi/lo)
    k_gemm<<<gP, 256, SMEM_BYTES>>>(xh, xl, wh, wl, sf0, sh0, sl0, bq, 1.0f,
                                    HD, HD, 0, 0, 0, 0, 0, 0);
    // k -> tmpf + kh/kl; transpose to kth/ktl
    k_gemm<<<gP, 256, SMEM_BYTES>>>(xh, xl, wh + nw, wl + nw, tmpf, kh, kl, bk, 1.0f,
                                    HD, HD, 0, 0, 0, 0, 0, 0);
    k_tcvt<<<gT, bT>>>(tmpf, kth, ktl);
    // v -> tmpf; transpose to vth/vtl   (launch 6 = k_gemm, profiled by ncu -s 5)
    k_gemm<<<gP, 256, SMEM_BYTES>>>(xh, xl, wh + 2 * nw, wl + 2 * nw, tmpf,
                                    nullptr, nullptr, bv, 1.0f,
                                    HD, HD, 0, 0, 0, 0, 0, 0);
    k_tcvt<<<gT, bT>>>(tmpf, vth, vtl);

    for (int it = 0; it < 5; it++) {
        k_gemm<<<gS, 256, SMEM_BYTES>>>(nullptr, nullptr, kh, kl, sc, nullptr, nullptr,
                                        nullptr, KSCALE, HD, SQ, aS, aS, cS, 1, 0, 1);
        k_softmax<<<NB * SQ, 256>>>(1);
        k_gemm<<<gV, 256, SMEM_BYTES>>>(ph, pl, kth, ktl, nullptr, nullptr, nullptr,
                                        nullptr, 1.0f, SQ, HD, cS, aS, aS, 0, 1, 1);
        k_finalize<<<1, 1>>>();
    }

    // readout vs values, then output projection
    k_gemm<<<gS, 256, SMEM_BYTES>>>(nullptr, nullptr, kh, kl, sc, nullptr, nullptr,
                                    nullptr, KSCALE, HD, SQ, aS, aS, cS, 1, 0, 0);
    k_softmax<<<NB * SQ, 256>>>(0);
    k_gemm<<<gV, 256, SMEM_BYTES>>>(ph, pl, vth, vtl, nullptr, ath, atl,
                                    nullptr, 1.0f, SQ, HD, cS, aS, aS, 0, 0, 0);
    k_gemm<<<gP, 256, SMEM_BYTES>>>(ath, atl, wh + 3 * nw, wl + 3 * nw, out, nullptr, nullptr,
                                    bo, 1.0f, HD, HD, 0, 0, 0, 0, 0, 0);

    if (out_size > BSH) k_tail<<<1, 1>>>(out, out_size - BSH);
}

// round 11
// speedup vs baseline: 1.3740x; 1.3740x over previous
#include <cuda_runtime.h>
#include <cuda_bf16.h>
#include <math.h>
#include <stdint.h>

#define NB 4
#define SQ 2048
#define HD 512
#define BSH (NB * SQ * HD)
#define KSCALE 0.044194173824159216f
#define TB 10240            // one tile: 128 rows * 80 bytes
#define STG (4 * TB)        // 4 tiles per stage
#define SMEM_BYTES (2 * STG)

typedef __nv_bfloat16 bf16;
struct __align__(8) bf4 { __nv_bfloat162 a, b; };

// ---- scratch ----
__device__ float g_sf[2][BSH];
__device__ bf16  g_sh[2][BSH], g_sl[2][BSH];
__device__ bf16  g_xh[BSH], g_xl[BSH];
__device__ bf16  g_kh[BSH], g_kl[BSH];
__device__ bf16  g_kth[BSH], g_ktl[BSH];
__device__ bf16  g_vth[BSH], g_vtl[BSH];
__device__ bf16  g_ath[BSH], g_atl[BSH];
__device__ bf16  g_wh[4 * HD * HD], g_wl[4 * HD * HD];
__device__ float g_tmpf[BSH];
__device__ float g_scores[(size_t)NB * SQ * SQ];
__device__ bf16  g_ph[(size_t)NB * SQ * SQ], g_pl[(size_t)NB * SQ * SQ];
__device__ int   g_converged, g_iters, g_sel;
__device__ float g_sumd, g_sumn;

// ---- helpers ----
__device__ __forceinline__ uint32_t smem_u32(const void* p) {
    uint32_t a;
    asm("{ .reg .u64 t; cvta.to.shared.u64 t, %1; cvt.u32.u64 %0, t; }" : "=r"(a) : "l"(p));
    return a;
}
// NON-volatile ldmatrix: "memory" clobber keeps it ordered vs barriers/cp.async,
// but the compiler may interleave it with MMAs for latency hiding.
__device__ __forceinline__ void ldsm4(uint32_t* r, uint32_t addr) {
    asm("ldmatrix.sync.aligned.m8n8.x4.shared.b16 {%0,%1,%2,%3}, [%4];"
        : "=r"(r[0]), "=r"(r[1]), "=r"(r[2]), "=r"(r[3]) : "r"(addr) : "memory");
}
// NON-volatile MMA: pure register op, freely schedulable by the compiler.
__device__ __forceinline__ void mma16816(float* d, const uint32_t* a, const uint32_t* b) {
    asm("mma.sync.aligned.m16n8k16.row.col.f32.bf16.bf16.f32 "
        "{%0,%1,%2,%3}, {%4,%5,%6,%7}, {%8,%9}, {%0,%1,%2,%3};"
        : "+f"(d[0]), "+f"(d[1]), "+f"(d[2]), "+f"(d[3])
        : "r"(a[0]), "r"(a[1]), "r"(a[2]), "r"(a[3]), "r"(b[0]), "r"(b[1]));
}
__device__ __forceinline__ void cpa16(uint32_t s, const void* g) {
    asm volatile("cp.async.cg.shared.global [%0], [%1], 16;" :: "r"(s), "l"(g));
}
__device__ __forceinline__ void split2(float v, bf16& h, bf16& l) {
    h = __float2bfloat16(v);
    l = __float2bfloat16(v - __bfloat162float(h));
}

// ---- control ----
__global__ void k_init() {
    g_converged = 0; g_iters = 0; g_sel = 0; g_sumd = 0.0f; g_sumn = 0.0f;
}
__global__ void k_finalize() {
    if (g_converged) return;
    float delta = sqrtf(g_sumd) / (sqrtf(g_sumn) + 1e-8f);
    g_iters += 1;
    if (delta < 1e-4f) g_converged = 1;
    g_sel ^= 1;
    g_sumd = 0.0f; g_sumn = 0.0f;
}
__global__ void k_tail(float* out, int extra) {
    if (extra >= 1) out[BSH] = (float)g_iters;
    if (extra >= 2) out[BSH + 1] = g_converged ? 1.0f : 0.0f;
}

// ---- fused fp32 -> (hi,lo) bf16 for x + 4 weights ----
__global__ void k_cvt_all(const float* __restrict__ x,
                          const float* __restrict__ Wq, const float* __restrict__ Wk,
                          const float* __restrict__ Wv, const float* __restrict__ Wo) {
    const int nwb = (HD * HD) / 1024;
    int b = blockIdx.x;
    const float* src;
    bf16 *h, *l;
    int base;
    if (b < BSH / 1024) {
        src = x; h = g_xh; l = g_xl; base = b * 1024;
    } else {
        int wb = b - BSH / 1024;
        int wi = wb / nwb;
        base = (wb - wi * nwb) * 1024;
        src = (wi == 0) ? Wq : (wi == 1) ? Wk : (wi == 2) ? Wv : Wo;
        h = g_wh + wi * HD * HD; l = g_wl + wi * HD * HD;
    }
    int i = base + threadIdx.x * 4;
    float4 v = *(const float4*)(src + i);
    bf4 hv, lv;
    split2(v.x, hv.a.x, lv.a.x);
    split2(v.y, hv.a.y, lv.a.y);
    split2(v.z, hv.b.x, lv.b.x);
    split2(v.w, hv.b.y, lv.b.y);
    *(bf4*)(h + i) = hv;
    *(bf4*)(l + i) = lv;
}

// ---- transpose-convert fp32 [B,S,H] -> bf16 hi/lo [B,H,S] ----
__global__ void k_tcvt(const float* __restrict__ src, bf16* __restrict__ th,
                       bf16* __restrict__ tl) {
    __shared__ float t[32][33];
    const int z = blockIdx.z;
    const float* s = src + (size_t)z * SQ * HD;
    const int h0 = blockIdx.x * 32, s0 = blockIdx.y * 32;
    const int tx = threadIdx.x, ty = threadIdx.y;
    for (int r = ty; r < 32; r += 8) t[r][tx] = s[(size_t)(s0 + r) * HD + h0 + tx];
    __syncthreads();
    for (int r = ty; r < 32; r += 8) {
        float v = t[tx][r];
        size_t o = (size_t)z * HD * SQ + (size_t)(h0 + r) * SQ + s0 + tx;
        bf16 hh, ll;
        split2(v, hh, ll);
        th[o] = hh;
        tl[o] = ll;
    }
}

// ---- register softmax: row of 2048, 256 threads ----
__global__ void __launch_bounds__(256)
k_softmax(int guard) {
    if (guard && g_converged) return;
    const size_t base = (size_t)blockIdx.x * SQ;
    const float4* r4 = (const float4*)(g_scores + base);
    const int tid = threadIdx.x, lane = tid & 31, w = tid >> 5;
    __shared__ float wr[16];

    float4 a = r4[tid], b = r4[tid + 256];
    float m = fmaxf(fmaxf(fmaxf(a.x, a.y), fmaxf(a.z, a.w)),
                    fmaxf(fmaxf(b.x, b.y), fmaxf(b.z, b.w)));
#pragma unroll
    for (int o = 16; o; o >>= 1) m = fmaxf(m, __shfl_xor_sync(0xffffffffu, m, o));
    if (lane == 0) wr[w] = m;
    __syncthreads();
    float mm = wr[0];
#pragma unroll
    for (int i = 1; i < 8; i++) mm = fmaxf(mm, wr[i]);

    float e[8];
    e[0] = __expf(a.x - mm); e[1] = __expf(a.y - mm);
    e[2] = __expf(a.z - mm); e[3] = __expf(a.w - mm);
    e[4] = __expf(b.x - mm); e[5] = __expf(b.y - mm);
    e[6] = __expf(b.z - mm); e[7] = __expf(b.w - mm);
    float s = e[0] + e[1] + e[2] + e[3] + e[4] + e[5] + e[6] + e[7];
#pragma unroll
    for (int o = 16; o; o >>= 1) s += __shfl_xor_sync(0xffffffffu, s, o);
    if (lane == 0) wr[8 + w] = s;
    __syncthreads();
    float tot = 0.0f;
#pragma unroll
    for (int i = 0; i < 8; i++) tot += wr[8 + i];
    const float inv = 1.0f / tot;

    bf4* ph4 = (bf4*)(g_ph + base);
    bf4* pl4 = (bf4*)(g_pl + base);
#pragma unroll
    for (int g = 0; g < 2; g++) {
        bf4 hv, lv;
        split2(e[g * 4 + 0] * inv, hv.a.x, lv.a.x);
        split2(e[g * 4 + 1] * inv, hv.a.y, lv.a.y);
        split2(e[g * 4 + 2] * inv, hv.b.x, lv.b.x);
        split2(e[g * 4 + 3] * inv, hv.b.y, lv.b.y);
        ph4[tid + g * 256] = hv;
        pl4[tid + g * 256] = lv;
    }
}

// ---- cp.async one 128x32 bf16 tile into smem (row stride 80B) ----
__device__ __forceinline__ void cpa_tile(uint32_t sdst, const bf16* __restrict__ src,
                                         size_t row0, int k0, int ld, int tid) {
#pragma unroll
    for (int r = 0; r < 2; r++) {
        int seg = tid + r * 256;
        int row = seg >> 2, sc = seg & 3;
        cpa16(sdst + row * 80 + sc * 16,
              src + (row0 + row) * (size_t)ld + k0 + sc * 8);
    }
}

// ---- split-bf16 HMMA GEMM: C[128,128] = A[128,K] @ B[128,K]^T (all K-major) ----
// proven two-barrier double-buffered mainloop (R5/R9)
__global__ void __launch_bounds__(256, 2)
k_gemm(const bf16* __restrict__ Ah_, const bf16* __restrict__ Al_,
       const bf16* __restrict__ Bh_, const bf16* __restrict__ Bl_,
       float* Cf, bf16* Ch, bf16* Cl,
       const float* __restrict__ bias, float scale, int Ktot, int ldc,
       size_t aB, size_t bB, size_t cB, int am, int cm, int guard) {
    if (guard && g_converged) return;
    extern __shared__ char smem[];
    const uint32_t sb = smem_u32(smem);
    const int tid = threadIdx.x, lane = tid & 31, w = tid >> 5;
    const int warp_m = (w >> 1) * 32, warp_n = (w & 1) * 64;

    const int z = blockIdx.z;
    const bf16 *Ah = Ah_, *Al = Al_;
    if (am) { int s = g_sel; Ah = g_sh[s]; Al = g_sl[s]; }
    Ah += (size_t)z * aB; Al += (size_t)z * aB;
    const bf16* Bh = Bh_ + (size_t)z * bB;
    const bf16* Bl = Bl_ + (size_t)z * bB;
    const float* Cold = nullptr;
    if (cm) {
        int s = g_sel ^ 1;
        Cf = g_sf[s]; Ch = g_sh[s]; Cl = g_sl[s];
        Cold = g_sf[s ^ 1] + (size_t)z * cB;
    }
    if (Cf) Cf += (size_t)z * cB;
    if (Ch) { Ch += (size_t)z * cB; Cl += (size_t)z * cB; }

    const size_t row0 = (size_t)blockIdx.y * 128;
    const size_t nrow0 = (size_t)blockIdx.x * 128;
    const int n0 = blockIdx.x * 128;

    uint32_t offA[2], offB[4];
#pragma unroll
    for (int mt = 0; mt < 2; mt++)
        offA[mt] = (uint32_t)(warp_m + mt * 16 + (lane & 7) + 8 * ((lane >> 3) & 1)) * 80
                 + (uint32_t)(lane >> 4) * 16;
#pragma unroll
    for (int p = 0; p < 4; p++)
        offB[p] = (uint32_t)(warp_n + p * 16 + (lane & 7) + 8 * (lane >> 4)) * 80
                + (uint32_t)((lane >> 3) & 1) * 16;

    float acc[2][8][4];
#pragma unroll
    for (int mt = 0; mt < 2; mt++)
#pragma unroll
        for (int nt = 0; nt < 8; nt++)
#pragma unroll
            for (int i = 0; i < 4; i++) acc[mt][nt][i] = 0.0f;

    const int nch = Ktot >> 5;
    cpa_tile(sb,          Ah, row0,  0, Ktot, tid);
    cpa_tile(sb + TB,     Al, row0,  0, Ktot, tid);
    cpa_tile(sb + 2 * TB, Bh, nrow0, 0, Ktot, tid);
    cpa_tile(sb + 3 * TB, Bl, nrow0, 0, Ktot, tid);
    asm volatile("cp.async.commit_group;");

    for (int c = 0; c < nch; c++) {
        if (c + 1 < nch) {
            uint32_t s2 = sb + ((c + 1) & 1) * STG;
            int k0 = (c + 1) << 5;
            cpa_tile(s2,          Ah, row0,  k0, Ktot, tid);
            cpa_tile(s2 + TB,     Al, row0,  k0, Ktot, tid);
            cpa_tile(s2 + 2 * TB, Bh, nrow0, k0, Ktot, tid);
            cpa_tile(s2 + 3 * TB, Bl, nrow0, k0, Ktot, tid);
            asm volatile("cp.async.commit_group;");
            asm volatile("cp.async.wait_group 1;");
        } else {
            asm volatile("cp.async.wait_group 0;");
        }
        __syncthreads();

        const uint32_t ss = sb + (c & 1) * STG;
#pragma unroll
        for (int k16 = 0; k16 < 2; k16++) {
            const uint32_t kof = k16 * 32;
            uint32_t ah0[4], al0[4], ah1[4], al1[4];
            ldsm4(ah0, ss + offA[0] + kof);
            ldsm4(al0, ss + TB + offA[0] + kof);
            ldsm4(ah1, ss + offA[1] + kof);
            ldsm4(al1, ss + TB + offA[1] + kof);
#pragma unroll
            for (int p = 0; p < 4; p++) {
                uint32_t bh[4], bl[4];
                ldsm4(bh, ss + 2 * TB + offB[p] + kof);
                ldsm4(bl, ss + 3 * TB + offB[p] + kof);
#pragma unroll
                for (int sub = 0; sub < 2; sub++) {
                    const uint32_t* pbh = &bh[sub * 2];
                    const uint32_t* pbl = &bl[sub * 2];
                    int nt = p * 2 + sub;
                    mma16816(acc[0][nt], ah0, pbh);
                    mma16816(acc[0][nt], ah0, pbl);
                    mma16816(acc[0][nt], al0, pbh);
                    mma16816(acc[1][nt], ah1, pbh);
                    mma16816(acc[1][nt], ah1, pbl);
                    mma16816(acc[1][nt], al1, pbh);
                }
            }
        }
        __syncthreads();
    }

    // epilogue (+ fused Frobenius-delta partials when writing state)
    float sd = 0.0f, sn = 0.0f;
    const int cr = lane >> 2, cc = (lane & 3) * 2;
#pragma unroll
    for (int mt = 0; mt < 2; mt++) {
#pragma unroll
        for (int nt = 0; nt < 8; nt++) {
#pragma unroll
            for (int half = 0; half < 2; half++) {
                int row = warp_m + mt * 16 + cr + half * 8;
                int col = warp_n + nt * 8 + cc;
                float vx = acc[mt][nt][half * 2 + 0] * scale;
                float vy = acc[mt][nt][half * 2 + 1] * scale;
                int gc = n0 + col;
                if (bias) { vx += __ldg(bias + gc); vy += __ldg(bias + gc + 1); }
                size_t ci = (row0 + row) * (size_t)ldc + gc;
                if (Cf) { float2 o; o.x = vx; o.y = vy; *(float2*)(Cf + ci) = o; }
                if (Cold) {
                    float2 ov = *(const float2*)(Cold + ci);
                    float dx = vx - ov.x, dy = vy - ov.y;
                    sd += dx * dx + dy * dy;
                    sn += ov.x * ov.x + ov.y * ov.y;
                }
                if (Ch) {
                    __nv_bfloat162 hv, lv;
                    split2(vx, hv.x, lv.x);
                    split2(vy, hv.y, lv.y);
                    *(__nv_bfloat162*)(Ch + ci) = hv;
                    *(__nv_bfloat162*)(Cl + ci) = lv;
                }
            }
        }
    }
    if (Cold) {
#pragma unroll
        for (int o = 16; o; o >>= 1) {
            sd += __shfl_xor_sync(0xffffffffu, sd, o);
            sn += __shfl_xor_sync(0xffffffffu, sn, o);
        }
        float* rbuf = (float*)smem;
        __syncthreads();
        if (lane == 0) { rbuf[w] = sd; rbuf[8 + w] = sn; }
        __syncthreads();
        if (tid == 0) {
            float t1 = 0.0f, t2 = 0.0f;
#pragma unroll
            for (int i = 0; i < 8; i++) { t1 += rbuf[i]; t2 += rbuf[8 + i]; }
            atomicAdd(&g_sumd, t1);
            atomicAdd(&g_sumn, t2);
        }
    }
}

// ---- launch ----
extern "C" void kernel_launch(void* const* d_in, const int* in_sizes, int n_in,
                              void* d_out, int out_size) {
    const float* x  = (const float*)d_in[0];
    const float* Wq = (const float*)d_in[1];
    const float* bq = (const float*)d_in[2];
    const float* Wk = (const float*)d_in[3];
    const float* bk = (const float*)d_in[4];
    const float* Wv = (const float*)d_in[5];
    const float* bv = (const float*)d_in[6];
    const float* Wo = (const float*)d_in[7];
    const float* bo = (const float*)d_in[8];
    float* out = (float*)d_out;

    void* pv;
    cudaGetSymbolAddress(&pv, g_xh);   bf16* xh = (bf16*)pv;
    cudaGetSymbolAddress(&pv, g_xl);   bf16* xl = (bf16*)pv;
    cudaGetSymbolAddress(&pv, g_kh);   bf16* kh = (bf16*)pv;
    cudaGetSymbolAddress(&pv, g_kl);   bf16* kl = (bf16*)pv;
    cudaGetSymbolAddress(&pv, g_kth);  bf16* kth = (bf16*)pv;
    cudaGetSymbolAddress(&pv, g_ktl);  bf16* ktl = (bf16*)pv;
    cudaGetSymbolAddress(&pv, g_vth);  bf16* vth = (bf16*)pv;
    cudaGetSymbolAddress(&pv, g_vtl);  bf16* vtl = (bf16*)pv;
    cudaGetSymbolAddress(&pv, g_ath);  bf16* ath = (bf16*)pv;
    cudaGetSymbolAddress(&pv, g_atl);  bf16* atl = (bf16*)pv;
    cudaGetSymbolAddress(&pv, g_wh);   bf16* wh = (bf16*)pv;
    cudaGetSymbolAddress(&pv, g_wl);   bf16* wl = (bf16*)pv;
    cudaGetSymbolAddress(&pv, g_tmpf); float* tmpf = (float*)pv;
    cudaGetSymbolAddress(&pv, g_scores); float* sc = (float*)pv;
    cudaGetSymbolAddress(&pv, g_ph);   bf16* ph = (bf16*)pv;
    cudaGetSymbolAddress(&pv, g_pl);   bf16* pl = (bf16*)pv;
    cudaGetSymbolAddress(&pv, g_sf);   float* sf0 = (float*)pv;
    cudaGetSymbolAddress(&pv, g_sh);   bf16* sh0 = (bf16*)pv;
    cudaGetSymbolAddress(&pv, g_sl);   bf16* sl0 = (bf16*)pv;

    cudaFuncSetAttribute(k_gemm, cudaFuncAttributeMaxDynamicSharedMemorySize, SMEM_BYTES);

    const int nw = HD * HD;
    const dim3 gP(4, 64, 1);
    const dim3 gS(16, 16, 4);
    const dim3 gV(4, 16, 4);
    const dim3 gT(16, 64, 4);
    const dim3 bT(32, 8);
    const size_t aS = (size_t)SQ * HD, cS = (size_t)SQ * SQ;

    k_init<<<1, 1>>>();
    k_cvt_all<<<BSH / 1024 + 4 * (nw / 1024), 256>>>(x, Wq, Wk, Wv, Wo);

    // q -> state slot 0 (fp32 + hi/lo)
    k_gemm<<<gP, 256, SMEM_BYTES>>>(xh, xl, wh, wl, sf0, sh0, sl0, bq, 1.0f,
                                    HD, HD, 0, 0, 0, 0, 0, 0);
    // k -> tmpf + kh/kl; transpose to kth/ktl
    k_gemm<<<gP, 256, SMEM_BYTES>>>(xh, xl, wh + nw, wl + nw, tmpf, kh, kl, bk, 1.0f,
                                    HD, HD, 0, 0, 0, 0, 0, 0);
    k_tcvt<<<gT, bT>>>(tmpf, kth, ktl);
    // v -> tmpf; transpose to vth/vtl   (launch 6 = k_gemm, profiled by ncu -s 5)
    k_gemm<<<gP, 256, SMEM_BYTES>>>(xh, xl, wh + 2 * nw, wl + 2 * nw, tmpf,
                                    nullptr, nullptr, bv, 1.0f,
                                    HD, HD, 0, 0, 0, 0, 0, 0);
    k_tcvt<<<gT, bT>>>(tmpf, vth, vtl);

    for (int it = 0; it < 5; it++) {
        k_gemm<<<gS, 256, SMEM_BYTES>>>(nullptr, nullptr, kh, kl, sc, nullptr, nullptr,
                                        nullptr, KSCALE, HD, SQ, aS, aS, cS, 1, 0, 1);
        k_softmax<<<NB * SQ, 256>>>(1);
        k_gemm<<<gV, 256, SMEM_BYTES>>>(ph, pl, kth, ktl, nullptr, nullptr, nullptr,
                                        nullptr, 1.0f, SQ, HD, cS, aS, aS, 0, 1, 1);
        k_finalize<<<1, 1>>>();
    }

    // readout vs values, then output projection
    k_gemm<<<gS, 256, SMEM_BYTES>>>(nullptr, nullptr, kh, kl, sc, nullptr, nullptr,
                                    nullptr, KSCALE, HD, SQ, aS, aS, cS, 1, 0, 0);
    k_softmax<<<NB * SQ, 256>>>(0);
    k_gemm<<<gV, 256, SMEM_BYTES>>>(ph, pl, vth, vtl, nullptr, ath, atl,
                                    nullptr, 1.0f, SQ, HD, cS, aS, aS, 0, 0, 0);
    k_gemm<<<gP, 256, SMEM_BYTES>>>(ath, atl, wh + 3 * nw, wl + 3 * nw, out, nullptr, nullptr,
                                    bo, 1.0f, HD, HD, 0, 0, 0, 0, 0, 0);

    if (out_size > BSH) k_tail<<<1, 1>>>(out, out_size - BSH);
}